// round 13
// baseline (speedup 1.0000x reference)
#include <cuda_runtime.h>
#include <cuda_fp16.h>
#include <cstdint>

#define NB   16
#define NN   10000
#define NE   320000
#define CIN  32
#define COUT 64
#define CC   96            // CIN + COUT
#define BC   1536          // NB*CC  (features per node, conv layout)
#define BC2  768           // half2 pairs per node row
#define BC4  192           // int4 per node row
#define MROWS 160000       // NN*NB

#define DEG_BLOCKS  1250           // NE/256
#define FEAT_PAIRS  (NN * BC / 2)
#define FEAT_BLOCKS (FEAT_PAIRS / 256)

// ---------------- static scratch (zero-init at load, re-zeroed at tail) ----------------
__device__ __align__(16) __half g_feat[5][NN * BC];   // x0, x1f, x1b, x2f, x2b (fp16)
__device__ float  g_u[MROWS * 64];          // update gate u (sigmoid), compact
__device__ __align__(16) __half g_Bru[5 * 128 * CC];  // ru weights: [l][n][k] fp16
__device__ __align__(16) __half g_Bc [5 * 64  * CC];  // c  weights: [l][n][k] fp16
__device__ float  g_deg_f[NN], g_deg_b[NN];
__device__ int    g_cnt_f[NN], g_cnt_b[NN];
__device__ int    g_cur_f[NN], g_cur_b[NN];
__device__ int    g_rp_f[NN + 1], g_rp_b[NN + 1];
__device__ int2   g_csr_f[NE], g_csr_b[NE]; // (neighbor, weight as packed half2)
__device__ int    g_any_odd;                // dtype sniff: 0 => edge_index is int64

__device__ __forceinline__ int load_node(const int* ei, int idx, int is64) {
    return is64 ? ei[2 * idx] : ei[idx];   // little-endian int64 low word
}

// ---------------- fused preprocessing: deg/cnt (+dtype detect) || build feat0 ----------------
__global__ void pre_kernel(const int* __restrict__ ei, const float* __restrict__ ew,
                           const float* __restrict__ x, const float* __restrict__ hs) {
    if (blockIdx.x < DEG_BLOCKS) {
        __shared__ int s_any;
        if (threadIdx.x == 0) s_any = 0;
        __syncthreads();
        int any = 0;
        for (int j = 2 * threadIdx.x + 1; j < 8192; j += 512) any |= ei[j];
        if (any) atomicOr(&s_any, 1);
        __syncthreads();
        int is64 = (s_any == 0);
        if (blockIdx.x == 0 && threadIdx.x == 0) g_any_odd = s_any;

        int e = blockIdx.x * 256 + threadIdx.x;
        int s = load_node(ei, e, is64);
        int d = load_node(ei, NE + e, is64);
        float w = ew[e];
        atomicAdd(&g_deg_f[s], w);
        atomicAdd(&g_deg_b[d], w);
        atomicAdd(&g_cnt_f[d], 1);
        atomicAdd(&g_cnt_b[s], 1);
    } else {
        int p = (blockIdx.x - DEG_BLOCKS) * 256 + threadIdx.x;  // half2 pair index
        int n = p / BC2;
        int rem = p - n * BC2;
        int c = 2 * rem;
        int b = c / CC;
        int cc = c - b * CC;
        float v0, v1;
        if (cc < CIN) {
            const float* xp = x + (size_t)(b * NN + n) * CIN + cc;
            v0 = xp[0]; v1 = xp[1];
        } else {
            const float* hp = hs + (size_t)(b * NN + n) * COUT + (cc - CIN);
            v0 = hp[0]; v1 = hp[1];
        }
        reinterpret_cast<__half2*>(g_feat[0])[p] = __float22half2_rn(make_float2(v0, v1));
    }
}

// precompute transposed fp16 weights: Bh[(l*NOUT + n)*96 + k] = Wp[(k*5+l)*NOUT + n]
template <int NOUT>
__global__ void wprep_kernel(const float* __restrict__ Wp, __half* __restrict__ Bh) {
    int id = blockIdx.x * 256 + threadIdx.x;
    if (id >= 5 * NOUT * CC) return;
    int k = id % CC;
    int rest = id / CC;
    int n = rest % NOUT;
    int l = rest / NOUT;
    Bh[id] = __float2half(Wp[((size_t)k * 5 + l) * NOUT + n]);
}

__global__ void scan_kernel() {
    const int* cnt = (blockIdx.x == 0) ? g_cnt_f : g_cnt_b;
    int* rp        = (blockIdx.x == 0) ? g_rp_f  : g_rp_b;
    __shared__ int sm[1024];
    __shared__ int s_carry;
    if (threadIdx.x == 0) s_carry = 0;
    __syncthreads();
    for (int base = 0; base < NN; base += 1024) {
        int i = base + threadIdx.x;
        int v = (i < NN) ? cnt[i] : 0;
        sm[threadIdx.x] = v;
        __syncthreads();
        for (int ofs = 1; ofs < 1024; ofs <<= 1) {
            int t = (threadIdx.x >= ofs) ? sm[threadIdx.x - ofs] : 0;
            __syncthreads();
            sm[threadIdx.x] += t;
            __syncthreads();
        }
        int carry = s_carry;
        if (i < NN) rp[i] = carry + sm[threadIdx.x] - v;
        __syncthreads();
        if (threadIdx.x == 1023) s_carry = carry + sm[1023];
        __syncthreads();
    }
    if (threadIdx.x == 0) rp[NN] = s_carry;
}

__global__ void scatter_kernel(const int* __restrict__ ei,
                               const float* __restrict__ ew) {
    int e = blockIdx.x * blockDim.x + threadIdx.x;
    if (e >= NE) return;
    int is64 = (g_any_odd == 0);
    int s = load_node(ei, e, is64);
    int d = load_node(ei, NE + e, is64);
    float w = ew[e];
    __half2 wf = __float2half2_rn(w / g_deg_f[s]);   // packed half2 weight
    __half2 wb = __float2half2_rn(w / g_deg_b[d]);
    int p = atomicAdd(&g_cur_f[d], 1);
    g_csr_f[g_rp_f[d] + p] = make_int2(s, *reinterpret_cast<const int*>(&wf));
    int q = atomicAdd(&g_cur_b[s], 1);
    g_csr_b[g_rp_b[s] + q] = make_int2(d, *reinterpret_cast<const int*>(&wb));
}

// ---------------- propagation (round-8 proven shape) ----------------
__device__ __forceinline__ void hacc8(__half2* h, int4 v, __half2 w) {
    const __half2* x = reinterpret_cast<const __half2*>(&v);
#pragma unroll
    for (int q = 0; q < 4; q++) h[q] = __hfma2(x[q], w, h[q]);
}

__device__ __forceinline__ void flush8(float* a, __half2* h) {
#pragma unroll
    for (int q = 0; q < 4; q++) {
        float2 f = __half22float2(h[q]);
        a[2 * q]     += f.x;
        a[2 * q + 1] += f.y;
        h[q] = __half2half2(__ushort_as_half(0));
    }
}

__device__ __forceinline__ int4 pack8(const float* a) {
    int4 ov;
    __half2* oh = reinterpret_cast<__half2*>(&ov);
#pragma unroll
    for (int q = 0; q < 4; q++)
        oh[q] = __float22half2_rn(make_float2(a[2 * q], a[2 * q + 1]));
    return ov;
}

// stage 0: feat[1+dir] = P_dir feat0
// stage 1: feat[3+dir] = 2 P_dir feat[1+dir] - feat0
// Thread owns ONE int4 slot; NT = 192 (full) / 128 (hidden, remapped to hidden slots)
template <bool HONLY>
__global__ void __launch_bounds__(HONLY ? 128 : 192, HONLY ? 12 : 8)
prop_pair(int stage) {
    int dir = blockIdx.y;
    int in_idx  = (stage == 0) ? 0 : 1 + dir;
    int out_idx = (stage == 0) ? 1 + dir : 3 + dir;

    const int4* __restrict__ in  = reinterpret_cast<const int4*>(g_feat[in_idx]);
    int4* __restrict__ out       = reinterpret_cast<int4*>(g_feat[out_idx]);
    const int* __restrict__ rp   = dir ? g_rp_b : g_rp_f;
    const int2* __restrict__ csr = dir ? g_csr_b : g_csr_f;

    int node = blockIdx.x;
    int t = threadIdx.x;
    int idx = HONLY ? ((t >> 3) * 12 + 4 + (t & 7)) : t;

    int s = rp[node];
    int e = rp[node + 1];

    float a[8];
#pragma unroll
    for (int q = 0; q < 8; q++) a[q] = 0.f;
    __half2 h[4];
#pragma unroll
    for (int q = 0; q < 4; q++) h[q] = __half2half2(__ushort_as_half(0));

    int i = s;
    while (i < e) {
        int cend = min(i + 8, e);              // <=8 fp16 adds per chunk
        for (; i + 1 < cend; i += 2) {
            int2 e0 = __ldg(&csr[i]);
            int2 e1 = __ldg(&csr[i + 1]);
            int4 v0 = __ldg(in + e0.x * BC4 + idx);
            int4 v1 = __ldg(in + e1.x * BC4 + idx);
            hacc8(h, v0, *reinterpret_cast<const __half2*>(&e0.y));
            hacc8(h, v1, *reinterpret_cast<const __half2*>(&e1.y));
        }
        if (i < cend) {
            int2 ed = __ldg(&csr[i]); i++;
            int4 v = __ldg(in + ed.x * BC4 + idx);
            hacc8(h, v, *reinterpret_cast<const __half2*>(&ed.y));
        }
        flush8(a, h);
    }

    if (stage == 1) {
        int4 bv = reinterpret_cast<const int4*>(g_feat[0])[node * BC4 + idx];
        const __half2* f = reinterpret_cast<const __half2*>(&bv);
#pragma unroll
        for (int q = 0; q < 4; q++) {
            float2 g0 = __half22float2(f[q]);
            a[2 * q]     = 2.f * a[2 * q]     - g0.x;
            a[2 * q + 1] = 2.f * a[2 * q + 1] - g0.y;
        }
    }
    out[node * BC4 + idx] = pack8(a);
}

// ---------------- tensor-core GEMM: fp16 mma.m16n8k16, fp32 accumulate ----------------
// B now comes precomputed/transposed in fp16 (g_Bru / g_Bc): int4 smem fills.
template <int NOUT, bool ISRU>
__global__ void __launch_bounds__(256) gemm_tc(const __half* __restrict__ Bh,
                                               const float* __restrict__ bias,
                                               const float* __restrict__ hs,
                                               float* __restrict__ dout) {
    constexpr int WN = NOUT / 2;
    constexpr int NF = WN / 8;
    constexpr int ASTRIDE = 104;   // halves per A smem row
    constexpr int BSTRIDE = 104;   // halves per B smem row (52 words; conflict-free)

    __shared__ __align__(16) __half As[128 * ASTRIDE];
    __shared__ __align__(16) __half Bs[NOUT * BSTRIDE];

    int tid  = threadIdx.x;
    int w    = tid >> 5;
    int lane = tid & 31;
    int wm   = w >> 1;
    int wn   = w & 1;
    int g    = lane >> 2;
    int t    = lane & 3;
    int mRow = blockIdx.x * 128;

    const uint32_t* Aw = reinterpret_cast<const uint32_t*>(As);
    const uint32_t* Bw = reinterpret_cast<const uint32_t*>(Bs);

    float acc[2][NF][4];
#pragma unroll
    for (int mf = 0; mf < 2; mf++)
#pragma unroll
        for (int nf = 0; nf < NF; nf++)
#pragma unroll
            for (int j = 0; j < 4; j++) acc[mf][nf][j] = 0.f;

#pragma unroll 1
    for (int l = 0; l < 5; ++l) {
        __syncthreads();
        // A tile: 128 rows x 12 int4, coalesced
        const int4* Ag = reinterpret_cast<const int4*>(g_feat[l]) + (size_t)mRow * 12;
#pragma unroll
        for (int j = 0; j < 6; j++) {
            int id = j * 256 + tid;
            int r = id / 12, c = id % 12;
            *reinterpret_cast<int4*>(&As[r * ASTRIDE + c * 8]) = __ldg(&Ag[r * 12 + c]);
        }
        // B tile: NOUT rows x 12 int4 from precomputed fp16 weights
        {
            const int4* Bg = reinterpret_cast<const int4*>(Bh) + (size_t)l * NOUT * 12;
            constexpr int NB4T = NOUT * 12;          // 1536 (ru) / 768 (c)
#pragma unroll
            for (int j = 0; j < NB4T / 256; j++) {
                int id = j * 256 + tid;
                int n = id / 12, c = id % 12;
                *reinterpret_cast<int4*>(&Bs[n * BSTRIDE + c * 8]) = __ldg(&Bg[id]);
            }
        }
        __syncthreads();

#pragma unroll
        for (int ks = 0; ks < 6; ks++) {
            uint32_t a[2][4];
#pragma unroll
            for (int mf = 0; mf < 2; mf++) {
                int base = (wm * 32 + mf * 16 + g) * (ASTRIDE / 2) + ks * 8 + t;
                a[mf][0] = Aw[base];
                a[mf][1] = Aw[base + 8 * (ASTRIDE / 2)];
                a[mf][2] = Aw[base + 4];
                a[mf][3] = Aw[base + 8 * (ASTRIDE / 2) + 4];
            }
            uint32_t b[NF][2];
#pragma unroll
            for (int nf = 0; nf < NF; nf++) {
                int col = wn * WN + nf * 8 + g;
                int bb = col * (BSTRIDE / 2) + ks * 8 + t;
                b[nf][0] = Bw[bb];
                b[nf][1] = Bw[bb + 4];
            }
#pragma unroll
            for (int mf = 0; mf < 2; mf++)
#pragma unroll
                for (int nf = 0; nf < NF; nf++) {
                    asm volatile(
                        "mma.sync.aligned.m16n8k16.row.col.f32.f16.f16.f32 "
                        "{%0,%1,%2,%3}, {%4,%5,%6,%7}, {%8,%9}, {%0,%1,%2,%3};"
                        : "+f"(acc[mf][nf][0]), "+f"(acc[mf][nf][1]),
                          "+f"(acc[mf][nf][2]), "+f"(acc[mf][nf][3])
                        : "r"(a[mf][0]), "r"(a[mf][1]), "r"(a[mf][2]), "r"(a[mf][3]),
                          "r"(b[nf][0]), "r"(b[nf][1]));
                }
        }
    }

#pragma unroll
    for (int mf = 0; mf < 2; mf++) {
        int r0 = mRow + wm * 32 + mf * 16 + g;
#pragma unroll
        for (int nf = 0; nf < NF; nf++) {
            int c0 = wn * WN + nf * 8 + 2 * t;
#pragma unroll
            for (int jr = 0; jr < 2; jr++) {
                int row = r0 + jr * 8;              // n*16 + b
                int n = row >> 4;
                int b = row & 15;
                float v0 = acc[mf][nf][jr * 2]     + bias[c0];
                float v1 = acc[mf][nf][jr * 2 + 1] + bias[c0 + 1];
                if (ISRU) {
                    float s0 = 1.f / (1.f + expf(-v0));
                    float s1 = 1.f / (1.f + expf(-v1));
                    if (c0 < COUT) {            // r: write r*h into feat0 hidden slots
                        float2 h = *reinterpret_cast<const float2*>(
                            &hs[(b * NN + n) * COUT + c0]);
                        *reinterpret_cast<__half2*>(&g_feat[0][n * BC + b * CC + CIN + c0]) =
                            __float22half2_rn(make_float2(s0 * h.x, s1 * h.y));
                    } else {                    // u: compact buffer
                        *reinterpret_cast<float2*>(&g_u[row * 64 + (c0 - COUT)]) =
                            make_float2(s0, s1);
                    }
                } else {
                    float cv0 = tanhf(tanhf(v0));
                    float cv1 = tanhf(tanhf(v1));
                    float2 u = *reinterpret_cast<const float2*>(&g_u[row * 64 + c0]);
                    float2 h = *reinterpret_cast<const float2*>(
                        &hs[(b * NN + n) * COUT + c0]);
                    *reinterpret_cast<float2*>(&dout[(b * NN + n) * COUT + c0]) =
                        make_float2(u.x * h.x + (1.f - u.x) * cv0,
                                    u.y * h.y + (1.f - u.y) * cv1);
                }
            }
        }
    }
}

// tail reset so the next kernel_launch call sees zeroed accumulators
__global__ void zero_tail_kernel() {
    int i = blockIdx.x * blockDim.x + threadIdx.x;
    if (i < NN) {
        g_deg_f[i] = 0.f; g_deg_b[i] = 0.f;
        g_cnt_f[i] = 0;   g_cnt_b[i] = 0;
        g_cur_f[i] = 0;   g_cur_b[i] = 0;
    }
}

// ---------------- launch ----------------
extern "C" void kernel_launch(void* const* d_in, const int* in_sizes, int n_in,
                              void* d_out, int out_size) {
    const float* x        = (const float*)d_in[0];
    const float* hs       = (const float*)d_in[1];
    const int*   ei       = (const int*)d_in[2];
    const float* ew       = (const float*)d_in[3];
    const float* ru_param = (const float*)d_in[4];
    const float* ru_bias  = (const float*)d_in[5];
    const float* c_param  = (const float*)d_in[6];
    const float* c_bias   = (const float*)d_in[7];
    float* out = (float*)d_out;

    // preprocessing (counters are zero at entry: static init / previous tail)
    pre_kernel<<<DEG_BLOCKS + FEAT_BLOCKS, 256>>>(ei, ew, x, hs);
    wprep_kernel<128><<<(5 * 128 * CC + 255) / 256, 256>>>(ru_param, g_Bru);
    wprep_kernel<64><<<(5 * 64 * CC + 255) / 256, 256>>>(c_param, g_Bc);
    scan_kernel<<<2, 1024>>>();
    scatter_kernel<<<DEG_BLOCKS, 256>>>(ei, ew);

    // conv1 Chebyshev propagations (full 1536 channels), fwd+bwd fused per launch
    prop_pair<false><<<dim3(NN, 2), 192>>>(0);   // x1f, x1b
    prop_pair<false><<<dim3(NN, 2), 192>>>(1);   // x2f, x2b

    // ru gates; epilogue writes r*h into feat0 hidden slots and u into g_u
    gemm_tc<128, true><<<MROWS / 128, 256>>>(g_Bru, ru_bias, hs, nullptr);

    // conv2 Chebyshev propagations (hidden 1024 channels only)
    prop_pair<true><<<dim3(NN, 2), 128>>>(0);
    prop_pair<true><<<dim3(NN, 2), 128>>>(1);

    // c = tanh(tanh(cheb @ c_param + bias));  out = u*h + (1-u)*c
    gemm_tc<64, false><<<MROWS / 128, 256>>>(g_Bc, c_bias, hs, out);

    // reset accumulators for the next call
    zero_tail_kernel<<<(NN + 255) / 256, 256>>>();
}

// round 14
// speedup vs baseline: 1.4466x; 1.4466x over previous
#include <cuda_runtime.h>
#include <cuda_fp16.h>
#include <cstdint>

#define NB   16
#define NN   10000
#define NE   320000
#define CIN  32
#define COUT 64
#define CC   96            // CIN + COUT
#define BC   1536          // NB*CC  (features per node, conv layout)
#define BC2  768           // half2 pairs per node row
#define BC4  192           // int4 per node row
#define MROWS 160000       // NN*NB

#define DEG_BLOCKS  1250           // NE/256
#define FEAT_PAIRS  (NN * BC / 2)
#define FEAT_BLOCKS (FEAT_PAIRS / 256)

// ---------------- static scratch (zero-init at load, re-zeroed at tail) ----------------
__device__ __align__(16) __half g_feat[5][NN * BC];   // x0, x1f, x1b, x2f, x2b (fp16)
__device__ float  g_u[MROWS * 64];          // update gate u (sigmoid), compact
__device__ __align__(16) __half g_Bru[5 * 128 * CC];  // ru weights: [l][n][k] fp16
__device__ __align__(16) __half g_Bc [5 * 64  * CC];  // c  weights: [l][n][k] fp16
__device__ float  g_deg_f[NN], g_deg_b[NN];
__device__ int    g_cnt_f[NN], g_cnt_b[NN];
__device__ int    g_cur_f[NN], g_cur_b[NN];
__device__ int    g_rp_f[NN + 1], g_rp_b[NN + 1];
__device__ int2   g_csr_f[NE], g_csr_b[NE]; // (neighbor, weight as packed half2)
__device__ int    g_any_odd;                // dtype sniff: 0 => edge_index is int64

__device__ __forceinline__ int load_node(const int* ei, int idx, int is64) {
    return is64 ? ei[2 * idx] : ei[idx];   // little-endian int64 low word
}

// ---------------- fused preprocessing: deg/cnt (+dtype detect) || build feat0 ----------------
__global__ void pre_kernel(const int* __restrict__ ei, const float* __restrict__ ew,
                           const float* __restrict__ x, const float* __restrict__ hs) {
    if (blockIdx.x < DEG_BLOCKS) {
        __shared__ int s_any;
        if (threadIdx.x == 0) s_any = 0;
        __syncthreads();
        int any = 0;
        for (int j = 2 * threadIdx.x + 1; j < 8192; j += 512) any |= ei[j];
        if (any) atomicOr(&s_any, 1);
        __syncthreads();
        int is64 = (s_any == 0);
        if (blockIdx.x == 0 && threadIdx.x == 0) g_any_odd = s_any;

        int e = blockIdx.x * 256 + threadIdx.x;
        int s = load_node(ei, e, is64);
        int d = load_node(ei, NE + e, is64);
        float w = ew[e];
        atomicAdd(&g_deg_f[s], w);
        atomicAdd(&g_deg_b[d], w);
        atomicAdd(&g_cnt_f[d], 1);
        atomicAdd(&g_cnt_b[s], 1);
    } else {
        int p = (blockIdx.x - DEG_BLOCKS) * 256 + threadIdx.x;  // half2 pair index
        int n = p / BC2;
        int rem = p - n * BC2;
        int c = 2 * rem;
        int b = c / CC;
        int cc = c - b * CC;
        float v0, v1;
        if (cc < CIN) {
            const float* xp = x + (size_t)(b * NN + n) * CIN + cc;
            v0 = xp[0]; v1 = xp[1];
        } else {
            const float* hp = hs + (size_t)(b * NN + n) * COUT + (cc - CIN);
            v0 = hp[0]; v1 = hp[1];
        }
        reinterpret_cast<__half2*>(g_feat[0])[p] = __float22half2_rn(make_float2(v0, v1));
    }
}

// precompute transposed fp16 weights INTO DEVICE SYMBOL (never pass symbol from host!)
// Bh[(l*NOUT + n)*96 + k] = Wp[(k*5+l)*NOUT + n]
template <int NOUT>
__global__ void wprep_kernel(const float* __restrict__ Wp) {
    __half* Bh = (NOUT == 128) ? g_Bru : g_Bc;   // device-side symbol resolution
    int id = blockIdx.x * 256 + threadIdx.x;
    if (id >= 5 * NOUT * CC) return;
    int k = id % CC;
    int rest = id / CC;
    int n = rest % NOUT;
    int l = rest / NOUT;
    Bh[id] = __float2half(Wp[((size_t)k * 5 + l) * NOUT + n]);
}

__global__ void scan_kernel() {
    const int* cnt = (blockIdx.x == 0) ? g_cnt_f : g_cnt_b;
    int* rp        = (blockIdx.x == 0) ? g_rp_f  : g_rp_b;
    __shared__ int sm[1024];
    __shared__ int s_carry;
    if (threadIdx.x == 0) s_carry = 0;
    __syncthreads();
    for (int base = 0; base < NN; base += 1024) {
        int i = base + threadIdx.x;
        int v = (i < NN) ? cnt[i] : 0;
        sm[threadIdx.x] = v;
        __syncthreads();
        for (int ofs = 1; ofs < 1024; ofs <<= 1) {
            int t = (threadIdx.x >= ofs) ? sm[threadIdx.x - ofs] : 0;
            __syncthreads();
            sm[threadIdx.x] += t;
            __syncthreads();
        }
        int carry = s_carry;
        if (i < NN) rp[i] = carry + sm[threadIdx.x] - v;
        __syncthreads();
        if (threadIdx.x == 1023) s_carry = carry + sm[1023];
        __syncthreads();
    }
    if (threadIdx.x == 0) rp[NN] = s_carry;
}

__global__ void scatter_kernel(const int* __restrict__ ei,
                               const float* __restrict__ ew) {
    int e = blockIdx.x * blockDim.x + threadIdx.x;
    if (e >= NE) return;
    int is64 = (g_any_odd == 0);
    int s = load_node(ei, e, is64);
    int d = load_node(ei, NE + e, is64);
    float w = ew[e];
    __half2 wf = __float2half2_rn(w / g_deg_f[s]);   // packed half2 weight
    __half2 wb = __float2half2_rn(w / g_deg_b[d]);
    int p = atomicAdd(&g_cur_f[d], 1);
    g_csr_f[g_rp_f[d] + p] = make_int2(s, *reinterpret_cast<const int*>(&wf));
    int q = atomicAdd(&g_cur_b[s], 1);
    g_csr_b[g_rp_b[s] + q] = make_int2(d, *reinterpret_cast<const int*>(&wb));
}

// ---------------- propagation (round-8 proven shape) ----------------
__device__ __forceinline__ void hacc8(__half2* h, int4 v, __half2 w) {
    const __half2* x = reinterpret_cast<const __half2*>(&v);
#pragma unroll
    for (int q = 0; q < 4; q++) h[q] = __hfma2(x[q], w, h[q]);
}

__device__ __forceinline__ void flush8(float* a, __half2* h) {
#pragma unroll
    for (int q = 0; q < 4; q++) {
        float2 f = __half22float2(h[q]);
        a[2 * q]     += f.x;
        a[2 * q + 1] += f.y;
        h[q] = __half2half2(__ushort_as_half(0));
    }
}

__device__ __forceinline__ int4 pack8(const float* a) {
    int4 ov;
    __half2* oh = reinterpret_cast<__half2*>(&ov);
#pragma unroll
    for (int q = 0; q < 4; q++)
        oh[q] = __float22half2_rn(make_float2(a[2 * q], a[2 * q + 1]));
    return ov;
}

// stage 0: feat[1+dir] = P_dir feat0
// stage 1: feat[3+dir] = 2 P_dir feat[1+dir] - feat0
template <bool HONLY>
__global__ void __launch_bounds__(HONLY ? 128 : 192, HONLY ? 12 : 8)
prop_pair(int stage) {
    int dir = blockIdx.y;
    int in_idx  = (stage == 0) ? 0 : 1 + dir;
    int out_idx = (stage == 0) ? 1 + dir : 3 + dir;

    const int4* __restrict__ in  = reinterpret_cast<const int4*>(g_feat[in_idx]);
    int4* __restrict__ out       = reinterpret_cast<int4*>(g_feat[out_idx]);
    const int* __restrict__ rp   = dir ? g_rp_b : g_rp_f;
    const int2* __restrict__ csr = dir ? g_csr_b : g_csr_f;

    int node = blockIdx.x;
    int t = threadIdx.x;
    int idx = HONLY ? ((t >> 3) * 12 + 4 + (t & 7)) : t;

    int s = rp[node];
    int e = rp[node + 1];

    float a[8];
#pragma unroll
    for (int q = 0; q < 8; q++) a[q] = 0.f;
    __half2 h[4];
#pragma unroll
    for (int q = 0; q < 4; q++) h[q] = __half2half2(__ushort_as_half(0));

    int i = s;
    while (i < e) {
        int cend = min(i + 8, e);              // <=8 fp16 adds per chunk
        for (; i + 1 < cend; i += 2) {
            int2 e0 = __ldg(&csr[i]);
            int2 e1 = __ldg(&csr[i + 1]);
            int4 v0 = __ldg(in + e0.x * BC4 + idx);
            int4 v1 = __ldg(in + e1.x * BC4 + idx);
            hacc8(h, v0, *reinterpret_cast<const __half2*>(&e0.y));
            hacc8(h, v1, *reinterpret_cast<const __half2*>(&e1.y));
        }
        if (i < cend) {
            int2 ed = __ldg(&csr[i]); i++;
            int4 v = __ldg(in + ed.x * BC4 + idx);
            hacc8(h, v, *reinterpret_cast<const __half2*>(&ed.y));
        }
        flush8(a, h);
    }

    if (stage == 1) {
        int4 bv = reinterpret_cast<const int4*>(g_feat[0])[node * BC4 + idx];
        const __half2* f = reinterpret_cast<const __half2*>(&bv);
#pragma unroll
        for (int q = 0; q < 4; q++) {
            float2 g0 = __half22float2(f[q]);
            a[2 * q]     = 2.f * a[2 * q]     - g0.x;
            a[2 * q + 1] = 2.f * a[2 * q + 1] - g0.y;
        }
    }
    out[node * BC4 + idx] = pack8(a);
}

// ---------------- tensor-core GEMM: fp16 mma.m16n8k16, fp32 accumulate ----------------
// B from precomputed fp16 device symbols (resolved IN DEVICE CODE).
template <int NOUT, bool ISRU>
__global__ void __launch_bounds__(256) gemm_tc(const float* __restrict__ bias,
                                               const float* __restrict__ hs,
                                               float* __restrict__ dout) {
    constexpr int WN = NOUT / 2;
    constexpr int NF = WN / 8;
    constexpr int ASTRIDE = 104;   // halves per A smem row
    constexpr int BSTRIDE = 104;   // halves per B smem row (52 words; conflict-free)

    __shared__ __align__(16) __half As[128 * ASTRIDE];
    __shared__ __align__(16) __half Bs[NOUT * BSTRIDE];

    const __half* __restrict__ Bh = ISRU ? g_Bru : g_Bc;   // device-side symbol

    int tid  = threadIdx.x;
    int w    = tid >> 5;
    int lane = tid & 31;
    int wm   = w >> 1;
    int wn   = w & 1;
    int g    = lane >> 2;
    int t    = lane & 3;
    int mRow = blockIdx.x * 128;

    const uint32_t* Aw = reinterpret_cast<const uint32_t*>(As);
    const uint32_t* Bw = reinterpret_cast<const uint32_t*>(Bs);

    float acc[2][NF][4];
#pragma unroll
    for (int mf = 0; mf < 2; mf++)
#pragma unroll
        for (int nf = 0; nf < NF; nf++)
#pragma unroll
            for (int j = 0; j < 4; j++) acc[mf][nf][j] = 0.f;

#pragma unroll 1
    for (int l = 0; l < 5; ++l) {
        __syncthreads();
        // A tile: 128 rows x 12 int4, coalesced
        const int4* Ag = reinterpret_cast<const int4*>(g_feat[l]) + (size_t)mRow * 12;
#pragma unroll
        for (int j = 0; j < 6; j++) {
            int id = j * 256 + tid;
            int r = id / 12, c = id % 12;
            *reinterpret_cast<int4*>(&As[r * ASTRIDE + c * 8]) = __ldg(&Ag[r * 12 + c]);
        }
        // B tile: NOUT rows x 12 int4 from precomputed fp16 weights (L2-resident)
        {
            const int4* Bg = reinterpret_cast<const int4*>(Bh) + (size_t)l * NOUT * 12;
            constexpr int NB4T = NOUT * 12;          // 1536 (ru) / 768 (c)
#pragma unroll
            for (int j = 0; j < NB4T / 256; j++) {
                int id = j * 256 + tid;
                int n = id / 12, c = id % 12;
                *reinterpret_cast<int4*>(&Bs[n * BSTRIDE + c * 8]) = __ldg(&Bg[id]);
            }
        }
        __syncthreads();

#pragma unroll
        for (int ks = 0; ks < 6; ks++) {
            uint32_t a[2][4];
#pragma unroll
            for (int mf = 0; mf < 2; mf++) {
                int base = (wm * 32 + mf * 16 + g) * (ASTRIDE / 2) + ks * 8 + t;
                a[mf][0] = Aw[base];
                a[mf][1] = Aw[base + 8 * (ASTRIDE / 2)];
                a[mf][2] = Aw[base + 4];
                a[mf][3] = Aw[base + 8 * (ASTRIDE / 2) + 4];
            }
            uint32_t b[NF][2];
#pragma unroll
            for (int nf = 0; nf < NF; nf++) {
                int col = wn * WN + nf * 8 + g;
                int bb = col * (BSTRIDE / 2) + ks * 8 + t;
                b[nf][0] = Bw[bb];
                b[nf][1] = Bw[bb + 4];
            }
#pragma unroll
            for (int mf = 0; mf < 2; mf++)
#pragma unroll
                for (int nf = 0; nf < NF; nf++) {
                    asm volatile(
                        "mma.sync.aligned.m16n8k16.row.col.f32.f16.f16.f32 "
                        "{%0,%1,%2,%3}, {%4,%5,%6,%7}, {%8,%9}, {%0,%1,%2,%3};"
                        : "+f"(acc[mf][nf][0]), "+f"(acc[mf][nf][1]),
                          "+f"(acc[mf][nf][2]), "+f"(acc[mf][nf][3])
                        : "r"(a[mf][0]), "r"(a[mf][1]), "r"(a[mf][2]), "r"(a[mf][3]),
                          "r"(b[nf][0]), "r"(b[nf][1]));
                }
        }
    }

#pragma unroll
    for (int mf = 0; mf < 2; mf++) {
        int r0 = mRow + wm * 32 + mf * 16 + g;
#pragma unroll
        for (int nf = 0; nf < NF; nf++) {
            int c0 = wn * WN + nf * 8 + 2 * t;
#pragma unroll
            for (int jr = 0; jr < 2; jr++) {
                int row = r0 + jr * 8;              // n*16 + b
                int n = row >> 4;
                int b = row & 15;
                float v0 = acc[mf][nf][jr * 2]     + bias[c0];
                float v1 = acc[mf][nf][jr * 2 + 1] + bias[c0 + 1];
                if (ISRU) {
                    float s0 = 1.f / (1.f + expf(-v0));
                    float s1 = 1.f / (1.f + expf(-v1));
                    if (c0 < COUT) {            // r: write r*h into feat0 hidden slots
                        float2 h = *reinterpret_cast<const float2*>(
                            &hs[(b * NN + n) * COUT + c0]);
                        *reinterpret_cast<__half2*>(&g_feat[0][n * BC + b * CC + CIN + c0]) =
                            __float22half2_rn(make_float2(s0 * h.x, s1 * h.y));
                    } else {                    // u: compact buffer
                        *reinterpret_cast<float2*>(&g_u[row * 64 + (c0 - COUT)]) =
                            make_float2(s0, s1);
                    }
                } else {
                    float cv0 = tanhf(tanhf(v0));
                    float cv1 = tanhf(tanhf(v1));
                    float2 u = *reinterpret_cast<const float2*>(&g_u[row * 64 + c0]);
                    float2 h = *reinterpret_cast<const float2*>(
                        &hs[(b * NN + n) * COUT + c0]);
                    *reinterpret_cast<float2*>(&dout[(b * NN + n) * COUT + c0]) =
                        make_float2(u.x * h.x + (1.f - u.x) * cv0,
                                    u.y * h.y + (1.f - u.y) * cv1);
                }
            }
        }
    }
}

// tail reset so the next kernel_launch call sees zeroed accumulators
__global__ void zero_tail_kernel() {
    int i = blockIdx.x * blockDim.x + threadIdx.x;
    if (i < NN) {
        g_deg_f[i] = 0.f; g_deg_b[i] = 0.f;
        g_cnt_f[i] = 0;   g_cnt_b[i] = 0;
        g_cur_f[i] = 0;   g_cur_b[i] = 0;
    }
}

// ---------------- launch ----------------
extern "C" void kernel_launch(void* const* d_in, const int* in_sizes, int n_in,
                              void* d_out, int out_size) {
    const float* x        = (const float*)d_in[0];
    const float* hs       = (const float*)d_in[1];
    const int*   ei       = (const int*)d_in[2];
    const float* ew       = (const float*)d_in[3];
    const float* ru_param = (const float*)d_in[4];
    const float* ru_bias  = (const float*)d_in[5];
    const float* c_param  = (const float*)d_in[6];
    const float* c_bias   = (const float*)d_in[7];
    float* out = (float*)d_out;

    // preprocessing (counters are zero at entry: static init / previous tail)
    pre_kernel<<<DEG_BLOCKS + FEAT_BLOCKS, 256>>>(ei, ew, x, hs);
    wprep_kernel<128><<<(5 * 128 * CC + 255) / 256, 256>>>(ru_param);
    wprep_kernel<64><<<(5 * 64 * CC + 255) / 256, 256>>>(c_param);
    scan_kernel<<<2, 1024>>>();
    scatter_kernel<<<DEG_BLOCKS, 256>>>(ei, ew);

    // conv1 Chebyshev propagations (full 1536 channels), fwd+bwd fused per launch
    prop_pair<false><<<dim3(NN, 2), 192>>>(0);   // x1f, x1b
    prop_pair<false><<<dim3(NN, 2), 192>>>(1);   // x2f, x2b

    // ru gates; epilogue writes r*h into feat0 hidden slots and u into g_u
    gemm_tc<128, true><<<MROWS / 128, 256>>>(ru_bias, hs, nullptr);

    // conv2 Chebyshev propagations (hidden 1024 channels only)
    prop_pair<true><<<dim3(NN, 2), 128>>>(0);
    prop_pair<true><<<dim3(NN, 2), 128>>>(1);

    // c = tanh(tanh(cheb @ c_param + bias));  out = u*h + (1-u)*c
    gemm_tc<64, false><<<MROWS / 128, 256>>>(c_bias, hs, out);

    // reset accumulators for the next call
    zero_tail_kernel<<<(NN + 255) / 256, 256>>>();
}

// round 15
// speedup vs baseline: 1.4949x; 1.0334x over previous
#include <cuda_runtime.h>
#include <cuda_fp16.h>
#include <cstdint>

#define NB   16
#define NN   10000
#define NE   320000
#define CIN  32
#define COUT 64
#define CC   96            // CIN + COUT
#define BC   1536          // NB*CC  (features per node, conv layout)
#define BC2  768           // half2 pairs per node row
#define BC4  192           // int4 per node row
#define MROWS 160000       // NN*NB

#define DEG_BLOCKS  1250           // NE/256
#define FEAT_PAIRS  (NN * BC / 2)
#define FEAT_BLOCKS (FEAT_PAIRS / 256)   // 30000
#define WRU_BLOCKS  240            // 5*128*96/256
#define WC_BLOCKS   120            // 5*64*96/256

// ---------------- static scratch (zero-init at load, re-zeroed at tail) ----------------
__device__ __align__(16) __half g_feat[5][NN * BC];   // x0, x1f, x1b, x2f, x2b (fp16)
__device__ float  g_u[MROWS * 64];          // update gate u (sigmoid), compact
__device__ __align__(16) __half g_Bru[5 * 128 * CC];  // ru weights: [l][n][k] fp16
__device__ __align__(16) __half g_Bc [5 * 64  * CC];  // c  weights: [l][n][k] fp16
__device__ float  g_deg_f[NN], g_deg_b[NN];
__device__ int    g_cnt_f[NN], g_cnt_b[NN];
__device__ int    g_cur_f[NN], g_cur_b[NN];
__device__ int    g_rp_f[NN + 1], g_rp_b[NN + 1];
__device__ int2   g_csr_f[NE], g_csr_b[NE]; // (neighbor, weight as packed half2)
__device__ int    g_any_odd;                // dtype sniff: 0 => edge_index is int64

__device__ __forceinline__ int load_node(const int* ei, int idx, int is64) {
    return is64 ? ei[2 * idx] : ei[idx];   // little-endian int64 low word
}

__device__ __forceinline__ uint32_t sptr(const void* p) {
    return (uint32_t)__cvta_generic_to_shared(p);
}

#define CP_ASYNC16(dst, src) \
    asm volatile("cp.async.cg.shared.global [%0], [%1], 16;" :: "r"(dst), "l"(src))
#define CP_COMMIT()  asm volatile("cp.async.commit_group;")
#define CP_WAIT0()   asm volatile("cp.async.wait_group 0;" ::: "memory")

// ---------------- fused preprocessing: deg/cnt || feat0 build || weight transpose ----------------
__global__ void pre_kernel(const int* __restrict__ ei, const float* __restrict__ ew,
                           const float* __restrict__ x, const float* __restrict__ hs,
                           const float* __restrict__ rup, const float* __restrict__ cp) {
    if (blockIdx.x < DEG_BLOCKS) {
        __shared__ int s_any;
        if (threadIdx.x == 0) s_any = 0;
        __syncthreads();
        int any = 0;
        for (int j = 2 * threadIdx.x + 1; j < 8192; j += 512) any |= ei[j];
        if (any) atomicOr(&s_any, 1);
        __syncthreads();
        int is64 = (s_any == 0);
        if (blockIdx.x == 0 && threadIdx.x == 0) g_any_odd = s_any;

        int e = blockIdx.x * 256 + threadIdx.x;
        int s = load_node(ei, e, is64);
        int d = load_node(ei, NE + e, is64);
        float w = ew[e];
        atomicAdd(&g_deg_f[s], w);
        atomicAdd(&g_deg_b[d], w);
        atomicAdd(&g_cnt_f[d], 1);
        atomicAdd(&g_cnt_b[s], 1);
    } else if (blockIdx.x < DEG_BLOCKS + FEAT_BLOCKS) {
        int p = (blockIdx.x - DEG_BLOCKS) * 256 + threadIdx.x;  // half2 pair index
        int n = p / BC2;
        int rem = p - n * BC2;
        int c = 2 * rem;
        int b = c / CC;
        int cc = c - b * CC;
        float v0, v1;
        if (cc < CIN) {
            const float* xp = x + (size_t)(b * NN + n) * CIN + cc;
            v0 = xp[0]; v1 = xp[1];
        } else {
            const float* hp = hs + (size_t)(b * NN + n) * COUT + (cc - CIN);
            v0 = hp[0]; v1 = hp[1];
        }
        reinterpret_cast<__half2*>(g_feat[0])[p] = __float22half2_rn(make_float2(v0, v1));
    } else if (blockIdx.x < DEG_BLOCKS + FEAT_BLOCKS + WRU_BLOCKS) {
        // g_Bru[(l*128+n)*96+k] = rup[(k*5+l)*128+n]
        int id = (blockIdx.x - DEG_BLOCKS - FEAT_BLOCKS) * 256 + threadIdx.x;
        int k = id % CC;
        int rest = id / CC;
        int n = rest % 128;
        int l = rest / 128;
        g_Bru[id] = __float2half(rup[((size_t)k * 5 + l) * 128 + n]);
    } else {
        int id = (blockIdx.x - DEG_BLOCKS - FEAT_BLOCKS - WRU_BLOCKS) * 256 + threadIdx.x;
        int k = id % CC;
        int rest = id / CC;
        int n = rest % 64;
        int l = rest / 64;
        g_Bc[id] = __float2half(cp[((size_t)k * 5 + l) * 64 + n]);
    }
}

// fast scan: per-thread 10-elem serial prefix + warp/block shuffle scan (2 syncs)
__global__ void scan_kernel() {
    const int* cnt = (blockIdx.x == 0) ? g_cnt_f : g_cnt_b;
    int* rp        = (blockIdx.x == 0) ? g_rp_f  : g_rp_b;
    int t = threadIdx.x;                   // 1024 threads
    int base = t * 10;
    int v[10];
    int sum = 0;
#pragma unroll
    for (int i = 0; i < 10; i++) {
        int idx = base + i;
        int xv = (idx < NN) ? cnt[idx] : 0;
        v[i] = sum;                        // exclusive within thread
        sum += xv;
    }
    int lane = t & 31, wd = t >> 5;
    int inc = sum;
#pragma unroll
    for (int o = 1; o < 32; o <<= 1) {
        int nv = __shfl_up_sync(0xffffffffu, inc, o);
        if (lane >= o) inc += nv;
    }
    __shared__ int wsum[32];
    if (lane == 31) wsum[wd] = inc;
    __syncthreads();
    if (wd == 0) {
        int ws = wsum[lane];
#pragma unroll
        for (int o = 1; o < 32; o <<= 1) {
            int nv = __shfl_up_sync(0xffffffffu, ws, o);
            if (lane >= o) ws += nv;
        }
        wsum[lane] = ws;
    }
    __syncthreads();
    int exc = inc - sum + (wd ? wsum[wd - 1] : 0);
#pragma unroll
    for (int i = 0; i < 10; i++) {
        int idx = base + i;
        if (idx < NN) rp[idx] = exc + v[i];
    }
    if (t == 1023) rp[NN] = wsum[31];
}

__global__ void scatter_kernel(const int* __restrict__ ei,
                               const float* __restrict__ ew) {
    int e = blockIdx.x * blockDim.x + threadIdx.x;
    if (e >= NE) return;
    int is64 = (g_any_odd == 0);
    int s = load_node(ei, e, is64);
    int d = load_node(ei, NE + e, is64);
    float w = ew[e];
    __half2 wf = __float2half2_rn(w / g_deg_f[s]);   // packed half2 weight
    __half2 wb = __float2half2_rn(w / g_deg_b[d]);
    int p = atomicAdd(&g_cur_f[d], 1);
    g_csr_f[g_rp_f[d] + p] = make_int2(s, *reinterpret_cast<const int*>(&wf));
    int q = atomicAdd(&g_cur_b[s], 1);
    g_csr_b[g_rp_b[s] + q] = make_int2(d, *reinterpret_cast<const int*>(&wb));
}

// ---------------- propagation (round-8 proven shape) ----------------
__device__ __forceinline__ void hacc8(__half2* h, int4 v, __half2 w) {
    const __half2* x = reinterpret_cast<const __half2*>(&v);
#pragma unroll
    for (int q = 0; q < 4; q++) h[q] = __hfma2(x[q], w, h[q]);
}

__device__ __forceinline__ void flush8(float* a, __half2* h) {
#pragma unroll
    for (int q = 0; q < 4; q++) {
        float2 f = __half22float2(h[q]);
        a[2 * q]     += f.x;
        a[2 * q + 1] += f.y;
        h[q] = __half2half2(__ushort_as_half(0));
    }
}

__device__ __forceinline__ int4 pack8(const float* a) {
    int4 ov;
    __half2* oh = reinterpret_cast<__half2*>(&ov);
#pragma unroll
    for (int q = 0; q < 4; q++)
        oh[q] = __float22half2_rn(make_float2(a[2 * q], a[2 * q + 1]));
    return ov;
}

// stage 0: feat[1+dir] = P_dir feat0
// stage 1: feat[3+dir] = 2 P_dir feat[1+dir] - feat0
template <bool HONLY>
__global__ void __launch_bounds__(HONLY ? 128 : 192, HONLY ? 12 : 8)
prop_pair(int stage) {
    int dir = blockIdx.y;
    int in_idx  = (stage == 0) ? 0 : 1 + dir;
    int out_idx = (stage == 0) ? 1 + dir : 3 + dir;

    const int4* __restrict__ in  = reinterpret_cast<const int4*>(g_feat[in_idx]);
    int4* __restrict__ out       = reinterpret_cast<int4*>(g_feat[out_idx]);
    const int* __restrict__ rp   = dir ? g_rp_b : g_rp_f;
    const int2* __restrict__ csr = dir ? g_csr_b : g_csr_f;

    int node = blockIdx.x;
    int t = threadIdx.x;
    int idx = HONLY ? ((t >> 3) * 12 + 4 + (t & 7)) : t;

    int s = rp[node];
    int e = rp[node + 1];

    float a[8];
#pragma unroll
    for (int q = 0; q < 8; q++) a[q] = 0.f;
    __half2 h[4];
#pragma unroll
    for (int q = 0; q < 4; q++) h[q] = __half2half2(__ushort_as_half(0));

    int i = s;
    while (i < e) {
        int cend = min(i + 8, e);              // <=8 fp16 adds per chunk
        for (; i + 1 < cend; i += 2) {
            int2 e0 = __ldg(&csr[i]);
            int2 e1 = __ldg(&csr[i + 1]);
            int4 v0 = __ldg(in + e0.x * BC4 + idx);
            int4 v1 = __ldg(in + e1.x * BC4 + idx);
            hacc8(h, v0, *reinterpret_cast<const __half2*>(&e0.y));
            hacc8(h, v1, *reinterpret_cast<const __half2*>(&e1.y));
        }
        if (i < cend) {
            int2 ed = __ldg(&csr[i]); i++;
            int4 v = __ldg(in + ed.x * BC4 + idx);
            hacc8(h, v, *reinterpret_cast<const __half2*>(&ed.y));
        }
        flush8(a, h);
    }

    if (stage == 1) {
        int4 bv = reinterpret_cast<const int4*>(g_feat[0])[node * BC4 + idx];
        const __half2* f = reinterpret_cast<const __half2*>(&bv);
#pragma unroll
        for (int q = 0; q < 4; q++) {
            float2 g0 = __half22float2(f[q]);
            a[2 * q]     = 2.f * a[2 * q]     - g0.x;
            a[2 * q + 1] = 2.f * a[2 * q + 1] - g0.y;
        }
    }
    out[node * BC4 + idx] = pack8(a);
}

// ---------------- tensor-core GEMM: fp16 mma, cp.async double-buffered ----------------
template <int NOUT, bool ISRU>
__global__ void __launch_bounds__(256) gemm_tc(const float* __restrict__ bias,
                                               const float* __restrict__ hs,
                                               float* __restrict__ dout) {
    constexpr int WN = NOUT / 2;
    constexpr int NF = WN / 8;
    constexpr int ASTRIDE = 104;   // halves per A smem row (conflict-free)
    constexpr int BSTRIDE = 104;
    constexpr int AW = 128 * ASTRIDE;
    constexpr int BW = NOUT * BSTRIDE;

    __shared__ __align__(16) __half As[2][AW];
    __shared__ __align__(16) __half Bs[2][BW];

    const __half* __restrict__ Bh = ISRU ? g_Bru : g_Bc;   // device-side symbol

    int tid  = threadIdx.x;
    int w    = tid >> 5;
    int lane = tid & 31;
    int wm   = w >> 1;
    int wn   = w & 1;
    int g    = lane >> 2;
    int t    = lane & 3;
    int mRow = blockIdx.x * 128;

    // async fill of layer l into stage s
    auto fill = [&](int l, int s) {
        const int4* Ag = reinterpret_cast<const int4*>(g_feat[l]) + (size_t)mRow * 12;
#pragma unroll
        for (int j = 0; j < 6; j++) {
            int id = j * 256 + tid;
            int r = id / 12, c = id % 12;
            CP_ASYNC16(sptr(&As[s][r * ASTRIDE + c * 8]), Ag + r * 12 + c);
        }
        const int4* Bg = reinterpret_cast<const int4*>(Bh) + (size_t)l * NOUT * 12;
#pragma unroll
        for (int j = 0; j < NOUT * 12 / 256; j++) {
            int id = j * 256 + tid;
            int n = id / 12, c = id % 12;
            CP_ASYNC16(sptr(&Bs[s][n * BSTRIDE + c * 8]), Bg + id);
        }
        CP_COMMIT();
    };

    float acc[2][NF][4];
#pragma unroll
    for (int mf = 0; mf < 2; mf++)
#pragma unroll
        for (int nf = 0; nf < NF; nf++)
#pragma unroll
            for (int j = 0; j < 4; j++) acc[mf][nf][j] = 0.f;

    fill(0, 0);
    CP_WAIT0();
    __syncthreads();

#pragma unroll 1
    for (int l = 0; l < 5; ++l) {
        int s = l & 1;
        if (l < 4) fill(l + 1, s ^ 1);     // overlap next-layer fill with compute

        const uint32_t* Aw = reinterpret_cast<const uint32_t*>(As[s]);
        const uint32_t* Bw = reinterpret_cast<const uint32_t*>(Bs[s]);
#pragma unroll
        for (int ks = 0; ks < 6; ks++) {
            uint32_t a[2][4];
#pragma unroll
            for (int mf = 0; mf < 2; mf++) {
                int base = (wm * 32 + mf * 16 + g) * (ASTRIDE / 2) + ks * 8 + t;
                a[mf][0] = Aw[base];
                a[mf][1] = Aw[base + 8 * (ASTRIDE / 2)];
                a[mf][2] = Aw[base + 4];
                a[mf][3] = Aw[base + 8 * (ASTRIDE / 2) + 4];
            }
            uint32_t b[NF][2];
#pragma unroll
            for (int nf = 0; nf < NF; nf++) {
                int col = wn * WN + nf * 8 + g;
                int bb = col * (BSTRIDE / 2) + ks * 8 + t;
                b[nf][0] = Bw[bb];
                b[nf][1] = Bw[bb + 4];
            }
#pragma unroll
            for (int mf = 0; mf < 2; mf++)
#pragma unroll
                for (int nf = 0; nf < NF; nf++) {
                    asm volatile(
                        "mma.sync.aligned.m16n8k16.row.col.f32.f16.f16.f32 "
                        "{%0,%1,%2,%3}, {%4,%5,%6,%7}, {%8,%9}, {%0,%1,%2,%3};"
                        : "+f"(acc[mf][nf][0]), "+f"(acc[mf][nf][1]),
                          "+f"(acc[mf][nf][2]), "+f"(acc[mf][nf][3])
                        : "r"(a[mf][0]), "r"(a[mf][1]), "r"(a[mf][2]), "r"(a[mf][3]),
                          "r"(b[nf][0]), "r"(b[nf][1]));
                }
        }
        if (l < 4) {
            CP_WAIT0();
            __syncthreads();
        }
    }

    // epilogue
#pragma unroll
    for (int mf = 0; mf < 2; mf++) {
        int r0 = mRow + wm * 32 + mf * 16 + g;
#pragma unroll
        for (int nf = 0; nf < NF; nf++) {
            int c0 = wn * WN + nf * 8 + 2 * t;
#pragma unroll
            for (int jr = 0; jr < 2; jr++) {
                int row = r0 + jr * 8;              // n*16 + b
                int n = row >> 4;
                int b = row & 15;
                float v0 = acc[mf][nf][jr * 2]     + bias[c0];
                float v1 = acc[mf][nf][jr * 2 + 1] + bias[c0 + 1];
                if (ISRU) {
                    float s0 = 1.f / (1.f + expf(-v0));
                    float s1 = 1.f / (1.f + expf(-v1));
                    if (c0 < COUT) {            // r: write r*h into feat0 hidden slots
                        float2 h = *reinterpret_cast<const float2*>(
                            &hs[(b * NN + n) * COUT + c0]);
                        *reinterpret_cast<__half2*>(&g_feat[0][n * BC + b * CC + CIN + c0]) =
                            __float22half2_rn(make_float2(s0 * h.x, s1 * h.y));
                    } else {                    // u: compact buffer
                        *reinterpret_cast<float2*>(&g_u[row * 64 + (c0 - COUT)]) =
                            make_float2(s0, s1);
                    }
                } else {
                    float cv0 = tanhf(tanhf(v0));
                    float cv1 = tanhf(tanhf(v1));
                    float2 u = *reinterpret_cast<const float2*>(&g_u[row * 64 + c0]);
                    float2 h = *reinterpret_cast<const float2*>(
                        &hs[(b * NN + n) * COUT + c0]);
                    *reinterpret_cast<float2*>(&dout[(b * NN + n) * COUT + c0]) =
                        make_float2(u.x * h.x + (1.f - u.x) * cv0,
                                    u.y * h.y + (1.f - u.y) * cv1);
                }
            }
        }
    }

    // fold tail reset into the last kernel (c-GEMM): zero counters for next call
    if (!ISRU) {
        int z = blockIdx.x * 256 + tid;
        if (z < NN) {
            g_deg_f[z] = 0.f; g_deg_b[z] = 0.f;
            g_cnt_f[z] = 0;   g_cnt_b[z] = 0;
            g_cur_f[z] = 0;   g_cur_b[z] = 0;
        }
    }
}

// ---------------- launch ----------------
extern "C" void kernel_launch(void* const* d_in, const int* in_sizes, int n_in,
                              void* d_out, int out_size) {
    const float* x        = (const float*)d_in[0];
    const float* hs       = (const float*)d_in[1];
    const int*   ei       = (const int*)d_in[2];
    const float* ew       = (const float*)d_in[3];
    const float* ru_param = (const float*)d_in[4];
    const float* ru_bias  = (const float*)d_in[5];
    const float* c_param  = (const float*)d_in[6];
    const float* c_bias   = (const float*)d_in[7];
    float* out = (float*)d_out;

    // preprocessing (counters are zero at entry: static init / previous call's tail)
    pre_kernel<<<DEG_BLOCKS + FEAT_BLOCKS + WRU_BLOCKS + WC_BLOCKS, 256>>>(
        ei, ew, x, hs, ru_param, c_param);
    scan_kernel<<<2, 1024>>>();
    scatter_kernel<<<DEG_BLOCKS, 256>>>(ei, ew);

    // conv1 Chebyshev propagations (full 1536 channels), fwd+bwd fused per launch
    prop_pair<false><<<dim3(NN, 2), 192>>>(0);   // x1f, x1b
    prop_pair<false><<<dim3(NN, 2), 192>>>(1);   // x2f, x2b

    // ru gates; epilogue writes r*h into feat0 hidden slots and u into g_u
    gemm_tc<128, true><<<MROWS / 128, 256>>>(ru_bias, hs, nullptr);

    // conv2 Chebyshev propagations (hidden 1024 channels only)
    prop_pair<true><<<dim3(NN, 2), 128>>>(0);
    prop_pair<true><<<dim3(NN, 2), 128>>>(1);

    // c = tanh(tanh(cheb @ c_param + bias));  out = u*h + (1-u)*c  (+ tail reset)
    gemm_tc<64, false><<<MROWS / 128, 256>>>(c_bias, hs, out);
}

// round 16
// speedup vs baseline: 1.6176x; 1.0821x over previous
#include <cuda_runtime.h>
#include <cuda_fp16.h>
#include <cstdint>

#define NB   16
#define NN   10000
#define NE   320000
#define CIN  32
#define COUT 64
#define CC   96            // CIN + COUT
#define BC   1536          // NB*CC  (features per node, conv layout)
#define BC2  768           // half2 pairs per node row
#define BC4  192           // int4 per node row
#define MROWS 160000       // NN*NB

#define DEG_BLOCKS  1250           // NE/256
#define FEAT_PAIRS  (NN * BC / 2)
#define FEAT_BLOCKS (FEAT_PAIRS / 256)   // 30000
#define WRU_BLOCKS  240            // 5*128*96/256
#define WC_BLOCKS   120            // 5*64*96/256

// ---------------- static scratch (zero-init at load, re-zeroed at tail) ----------------
__device__ __align__(16) __half g_feat[5][NN * BC];   // x0, x1f, x1b, x2f, x2b (fp16)
__device__ float  g_u[MROWS * 64];          // update gate u (sigmoid), compact
__device__ __align__(16) __half g_Bru[5 * 128 * CC];  // ru weights: [l][n][k] fp16
__device__ __align__(16) __half g_Bc [5 * 64  * CC];  // c  weights: [l][n][k] fp16
__device__ float  g_deg_f[NN], g_deg_b[NN];
__device__ int    g_cnt_f[NN], g_cnt_b[NN];
__device__ int    g_cur_f[NN], g_cur_b[NN];
__device__ int    g_rp_f[NN + 1], g_rp_b[NN + 1];
__device__ int2   g_csr_f[NE], g_csr_b[NE]; // (neighbor, weight as packed half2)
__device__ int    g_any_odd;                // dtype sniff: 0 => edge_index is int64

__device__ __forceinline__ int load_node(const int* ei, int idx, int is64) {
    return is64 ? ei[2 * idx] : ei[idx];   // little-endian int64 low word
}

__device__ __forceinline__ uint32_t sptr(const void* p) {
    return (uint32_t)__cvta_generic_to_shared(p);
}

#define CP_ASYNC16(dst, src) \
    asm volatile("cp.async.cg.shared.global [%0], [%1], 16;" :: "r"(dst), "l"(src))
#define CP_COMMIT()  asm volatile("cp.async.commit_group;")
#define CP_WAIT0()   asm volatile("cp.async.wait_group 0;" ::: "memory")

// ---------------- fused preprocessing: deg/cnt || feat0 build || weight transpose ----------------
__global__ void pre_kernel(const int* __restrict__ ei, const float* __restrict__ ew,
                           const float* __restrict__ x, const float* __restrict__ hs,
                           const float* __restrict__ rup, const float* __restrict__ cp) {
    if (blockIdx.x < DEG_BLOCKS) {
        __shared__ int s_any;
        if (threadIdx.x == 0) s_any = 0;
        __syncthreads();
        int any = 0;
        for (int j = 2 * threadIdx.x + 1; j < 8192; j += 512) any |= ei[j];
        if (any) atomicOr(&s_any, 1);
        __syncthreads();
        int is64 = (s_any == 0);
        if (blockIdx.x == 0 && threadIdx.x == 0) g_any_odd = s_any;

        int e = blockIdx.x * 256 + threadIdx.x;
        int s = load_node(ei, e, is64);
        int d = load_node(ei, NE + e, is64);
        float w = ew[e];
        atomicAdd(&g_deg_f[s], w);
        atomicAdd(&g_deg_b[d], w);
        atomicAdd(&g_cnt_f[d], 1);
        atomicAdd(&g_cnt_b[s], 1);
    } else if (blockIdx.x < DEG_BLOCKS + FEAT_BLOCKS) {
        int p = (blockIdx.x - DEG_BLOCKS) * 256 + threadIdx.x;  // half2 pair index
        int n = p / BC2;
        int rem = p - n * BC2;
        int c = 2 * rem;
        int b = c / CC;
        int cc = c - b * CC;
        float v0, v1;
        if (cc < CIN) {
            const float* xp = x + (size_t)(b * NN + n) * CIN + cc;
            v0 = xp[0]; v1 = xp[1];
        } else {
            const float* hp = hs + (size_t)(b * NN + n) * COUT + (cc - CIN);
            v0 = hp[0]; v1 = hp[1];
        }
        reinterpret_cast<__half2*>(g_feat[0])[p] = __float22half2_rn(make_float2(v0, v1));
    } else if (blockIdx.x < DEG_BLOCKS + FEAT_BLOCKS + WRU_BLOCKS) {
        // g_Bru[(l*128+n)*96+k] = rup[(k*5+l)*128+n]
        int id = (blockIdx.x - DEG_BLOCKS - FEAT_BLOCKS) * 256 + threadIdx.x;
        int k = id % CC;
        int rest = id / CC;
        int n = rest % 128;
        int l = rest / 128;
        g_Bru[id] = __float2half(rup[((size_t)k * 5 + l) * 128 + n]);
    } else {
        int id = (blockIdx.x - DEG_BLOCKS - FEAT_BLOCKS - WRU_BLOCKS) * 256 + threadIdx.x;
        int k = id % CC;
        int rest = id / CC;
        int n = rest % 64;
        int l = rest / 64;
        g_Bc[id] = __float2half(cp[((size_t)k * 5 + l) * 64 + n]);
    }
}

// fast scan: per-thread 10-elem serial prefix + warp/block shuffle scan (2 syncs)
__global__ void scan_kernel() {
    const int* cnt = (blockIdx.x == 0) ? g_cnt_f : g_cnt_b;
    int* rp        = (blockIdx.x == 0) ? g_rp_f  : g_rp_b;
    int t = threadIdx.x;                   // 1024 threads
    int base = t * 10;
    int v[10];
    int sum = 0;
#pragma unroll
    for (int i = 0; i < 10; i++) {
        int idx = base + i;
        int xv = (idx < NN) ? cnt[idx] : 0;
        v[i] = sum;                        // exclusive within thread
        sum += xv;
    }
    int lane = t & 31, wd = t >> 5;
    int inc = sum;
#pragma unroll
    for (int o = 1; o < 32; o <<= 1) {
        int nv = __shfl_up_sync(0xffffffffu, inc, o);
        if (lane >= o) inc += nv;
    }
    __shared__ int wsum[32];
    if (lane == 31) wsum[wd] = inc;
    __syncthreads();
    if (wd == 0) {
        int ws = wsum[lane];
#pragma unroll
        for (int o = 1; o < 32; o <<= 1) {
            int nv = __shfl_up_sync(0xffffffffu, ws, o);
            if (lane >= o) ws += nv;
        }
        wsum[lane] = ws;
    }
    __syncthreads();
    int exc = inc - sum + (wd ? wsum[wd - 1] : 0);
#pragma unroll
    for (int i = 0; i < 10; i++) {
        int idx = base + i;
        if (idx < NN) rp[idx] = exc + v[i];
    }
    if (t == 1023) rp[NN] = wsum[31];
}

__global__ void scatter_kernel(const int* __restrict__ ei,
                               const float* __restrict__ ew) {
    int e = blockIdx.x * blockDim.x + threadIdx.x;
    if (e >= NE) return;
    int is64 = (g_any_odd == 0);
    int s = load_node(ei, e, is64);
    int d = load_node(ei, NE + e, is64);
    float w = ew[e];
    __half2 wf = __float2half2_rn(w / g_deg_f[s]);   // packed half2 weight
    __half2 wb = __float2half2_rn(w / g_deg_b[d]);
    int p = atomicAdd(&g_cur_f[d], 1);
    g_csr_f[g_rp_f[d] + p] = make_int2(s, *reinterpret_cast<const int*>(&wf));
    int q = atomicAdd(&g_cur_b[s], 1);
    g_csr_b[g_rp_b[s] + q] = make_int2(d, *reinterpret_cast<const int*>(&wb));
}

// ---------------- propagation (round-8 proven shape, regs pinned) ----------------
__device__ __forceinline__ void hacc8(__half2* h, int4 v, __half2 w) {
    const __half2* x = reinterpret_cast<const __half2*>(&v);
#pragma unroll
    for (int q = 0; q < 4; q++) h[q] = __hfma2(x[q], w, h[q]);
}

__device__ __forceinline__ void flush8(float* a, __half2* h) {
#pragma unroll
    for (int q = 0; q < 4; q++) {
        float2 f = __half22float2(h[q]);
        a[2 * q]     += f.x;
        a[2 * q + 1] += f.y;
        h[q] = __half2half2(__ushort_as_half(0));
    }
}

__device__ __forceinline__ int4 pack8(const float* a) {
    int4 ov;
    __half2* oh = reinterpret_cast<__half2*>(&ov);
#pragma unroll
    for (int q = 0; q < 4; q++)
        oh[q] = __float22half2_rn(make_float2(a[2 * q], a[2 * q + 1]));
    return ov;
}

// stage 0: feat[1+dir] = P_dir feat0
// stage 1: feat[3+dir] = 2 P_dir feat[1+dir] - feat0
// launch_bounds minBlocks pins reg budget (34 full / 32 hidden) -> high occupancy
template <bool HONLY>
__global__ void __launch_bounds__(HONLY ? 128 : 192, HONLY ? 16 : 10)
prop_pair(int stage) {
    int dir = blockIdx.y;
    int in_idx  = (stage == 0) ? 0 : 1 + dir;
    int out_idx = (stage == 0) ? 1 + dir : 3 + dir;

    const int4* __restrict__ in  = reinterpret_cast<const int4*>(g_feat[in_idx]);
    int4* __restrict__ out       = reinterpret_cast<int4*>(g_feat[out_idx]);
    const int* __restrict__ rp   = dir ? g_rp_b : g_rp_f;
    const int2* __restrict__ csr = dir ? g_csr_b : g_csr_f;

    int node = blockIdx.x;
    int t = threadIdx.x;
    int idx = HONLY ? ((t >> 3) * 12 + 4 + (t & 7)) : t;

    int s = rp[node];
    int e = rp[node + 1];

    float a[8];
#pragma unroll
    for (int q = 0; q < 8; q++) a[q] = 0.f;
    __half2 h[4];
#pragma unroll
    for (int q = 0; q < 4; q++) h[q] = __half2half2(__ushort_as_half(0));

    int i = s;
    while (i < e) {
        int cend = min(i + 8, e);              // <=8 fp16 adds per chunk
        for (; i + 1 < cend; i += 2) {
            int2 e0 = __ldg(&csr[i]);
            int2 e1 = __ldg(&csr[i + 1]);
            int4 v0 = __ldg(in + e0.x * BC4 + idx);
            int4 v1 = __ldg(in + e1.x * BC4 + idx);
            hacc8(h, v0, *reinterpret_cast<const __half2*>(&e0.y));
            hacc8(h, v1, *reinterpret_cast<const __half2*>(&e1.y));
        }
        if (i < cend) {
            int2 ed = __ldg(&csr[i]); i++;
            int4 v = __ldg(in + ed.x * BC4 + idx);
            hacc8(h, v, *reinterpret_cast<const __half2*>(&ed.y));
        }
        flush8(a, h);
    }

    if (stage == 1) {
        int4 bv = reinterpret_cast<const int4*>(g_feat[0])[node * BC4 + idx];
        const __half2* f = reinterpret_cast<const __half2*>(&bv);
#pragma unroll
        for (int q = 0; q < 4; q++) {
            float2 g0 = __half22float2(f[q]);
            a[2 * q]     = 2.f * a[2 * q]     - g0.x;
            a[2 * q + 1] = 2.f * a[2 * q + 1] - g0.y;
        }
    }
    out[node * BC4 + idx] = pack8(a);
}

// ---------------- tensor-core GEMM: fp16 mma, cp.async double-buffered ----------------
template <int NOUT, bool ISRU>
__global__ void __launch_bounds__(256) gemm_tc(const float* __restrict__ bias,
                                               const float* __restrict__ hs,
                                               float* __restrict__ dout) {
    constexpr int WN = NOUT / 2;
    constexpr int NF = WN / 8;
    constexpr int ASTRIDE = 104;   // halves per A smem row (conflict-free)
    constexpr int BSTRIDE = 104;
    constexpr int AW = 128 * ASTRIDE;
    constexpr int BW = NOUT * BSTRIDE;

    __shared__ __align__(16) __half As[2][AW];
    __shared__ __align__(16) __half Bs[2][BW];

    const __half* __restrict__ Bh = ISRU ? g_Bru : g_Bc;   // device-side symbol

    int tid  = threadIdx.x;
    int w    = tid >> 5;
    int lane = tid & 31;
    int wm   = w >> 1;
    int wn   = w & 1;
    int g    = lane >> 2;
    int t    = lane & 3;
    int mRow = blockIdx.x * 128;

    // async fill of layer l into stage s
    auto fill = [&](int l, int s) {
        const int4* Ag = reinterpret_cast<const int4*>(g_feat[l]) + (size_t)mRow * 12;
#pragma unroll
        for (int j = 0; j < 6; j++) {
            int id = j * 256 + tid;
            int r = id / 12, c = id % 12;
            CP_ASYNC16(sptr(&As[s][r * ASTRIDE + c * 8]), Ag + r * 12 + c);
        }
        const int4* Bg = reinterpret_cast<const int4*>(Bh) + (size_t)l * NOUT * 12;
#pragma unroll
        for (int j = 0; j < NOUT * 12 / 256; j++) {
            int id = j * 256 + tid;
            int n = id / 12, c = id % 12;
            CP_ASYNC16(sptr(&Bs[s][n * BSTRIDE + c * 8]), Bg + id);
        }
        CP_COMMIT();
    };

    float acc[2][NF][4];
#pragma unroll
    for (int mf = 0; mf < 2; mf++)
#pragma unroll
        for (int nf = 0; nf < NF; nf++)
#pragma unroll
            for (int j = 0; j < 4; j++) acc[mf][nf][j] = 0.f;

    fill(0, 0);
    CP_WAIT0();
    __syncthreads();

#pragma unroll 1
    for (int l = 0; l < 5; ++l) {
        int s = l & 1;
        if (l < 4) fill(l + 1, s ^ 1);     // overlap next-layer fill with compute

        const uint32_t* Aw = reinterpret_cast<const uint32_t*>(As[s]);
        const uint32_t* Bw = reinterpret_cast<const uint32_t*>(Bs[s]);
#pragma unroll
        for (int ks = 0; ks < 6; ks++) {
            uint32_t a[2][4];
#pragma unroll
            for (int mf = 0; mf < 2; mf++) {
                int base = (wm * 32 + mf * 16 + g) * (ASTRIDE / 2) + ks * 8 + t;
                a[mf][0] = Aw[base];
                a[mf][1] = Aw[base + 8 * (ASTRIDE / 2)];
                a[mf][2] = Aw[base + 4];
                a[mf][3] = Aw[base + 8 * (ASTRIDE / 2) + 4];
            }
            uint32_t b[NF][2];
#pragma unroll
            for (int nf = 0; nf < NF; nf++) {
                int col = wn * WN + nf * 8 + g;
                int bb = col * (BSTRIDE / 2) + ks * 8 + t;
                b[nf][0] = Bw[bb];
                b[nf][1] = Bw[bb + 4];
            }
#pragma unroll
            for (int mf = 0; mf < 2; mf++)
#pragma unroll
                for (int nf = 0; nf < NF; nf++) {
                    asm volatile(
                        "mma.sync.aligned.m16n8k16.row.col.f32.f16.f16.f32 "
                        "{%0,%1,%2,%3}, {%4,%5,%6,%7}, {%8,%9}, {%0,%1,%2,%3};"
                        : "+f"(acc[mf][nf][0]), "+f"(acc[mf][nf][1]),
                          "+f"(acc[mf][nf][2]), "+f"(acc[mf][nf][3])
                        : "r"(a[mf][0]), "r"(a[mf][1]), "r"(a[mf][2]), "r"(a[mf][3]),
                          "r"(b[nf][0]), "r"(b[nf][1]));
                }
        }
        if (l < 4) {
            CP_WAIT0();
            __syncthreads();
        }
    }

    // epilogue
#pragma unroll
    for (int mf = 0; mf < 2; mf++) {
        int r0 = mRow + wm * 32 + mf * 16 + g;
#pragma unroll
        for (int nf = 0; nf < NF; nf++) {
            int c0 = wn * WN + nf * 8 + 2 * t;
#pragma unroll
            for (int jr = 0; jr < 2; jr++) {
                int row = r0 + jr * 8;              // n*16 + b
                int n = row >> 4;
                int b = row & 15;
                float v0 = acc[mf][nf][jr * 2]     + bias[c0];
                float v1 = acc[mf][nf][jr * 2 + 1] + bias[c0 + 1];
                if (ISRU) {
                    float s0 = 1.f / (1.f + expf(-v0));
                    float s1 = 1.f / (1.f + expf(-v1));
                    if (c0 < COUT) {            // r: write r*h into feat0 hidden slots
                        float2 h = *reinterpret_cast<const float2*>(
                            &hs[(b * NN + n) * COUT + c0]);
                        *reinterpret_cast<__half2*>(&g_feat[0][n * BC + b * CC + CIN + c0]) =
                            __float22half2_rn(make_float2(s0 * h.x, s1 * h.y));
                    } else {                    // u: compact buffer
                        *reinterpret_cast<float2*>(&g_u[row * 64 + (c0 - COUT)]) =
                            make_float2(s0, s1);
                    }
                } else {
                    float cv0 = tanhf(tanhf(v0));
                    float cv1 = tanhf(tanhf(v1));
                    float2 u = *reinterpret_cast<const float2*>(&g_u[row * 64 + c0]);
                    float2 h = *reinterpret_cast<const float2*>(
                        &hs[(b * NN + n) * COUT + c0]);
                    *reinterpret_cast<float2*>(&dout[(b * NN + n) * COUT + c0]) =
                        make_float2(u.x * h.x + (1.f - u.x) * cv0,
                                    u.y * h.y + (1.f - u.y) * cv1);
                }
            }
        }
    }

    // fold tail reset into the last kernel (c-GEMM): zero counters for next call
    if (!ISRU) {
        int z = blockIdx.x * 256 + tid;
        if (z < NN) {
            g_deg_f[z] = 0.f; g_deg_b[z] = 0.f;
            g_cnt_f[z] = 0;   g_cnt_b[z] = 0;
            g_cur_f[z] = 0;   g_cur_b[z] = 0;
        }
    }
}

// ---------------- launch ----------------
extern "C" void kernel_launch(void* const* d_in, const int* in_sizes, int n_in,
                              void* d_out, int out_size) {
    const float* x        = (const float*)d_in[0];
    const float* hs       = (const float*)d_in[1];
    const int*   ei       = (const int*)d_in[2];
    const float* ew       = (const float*)d_in[3];
    const float* ru_param = (const float*)d_in[4];
    const float* ru_bias  = (const float*)d_in[5];
    const float* c_param  = (const float*)d_in[6];
    const float* c_bias   = (const float*)d_in[7];
    float* out = (float*)d_out;

    // preprocessing (counters are zero at entry: static init / previous call's tail)
    pre_kernel<<<DEG_BLOCKS + FEAT_BLOCKS + WRU_BLOCKS + WC_BLOCKS, 256>>>(
        ei, ew, x, hs, ru_param, c_param);
    scan_kernel<<<2, 1024>>>();
    scatter_kernel<<<DEG_BLOCKS, 256>>>(ei, ew);

    // conv1 Chebyshev propagations (full 1536 channels), fwd+bwd fused per launch
    prop_pair<false><<<dim3(NN, 2), 192>>>(0);   // x1f, x1b
    prop_pair<false><<<dim3(NN, 2), 192>>>(1);   // x2f, x2b

    // ru gates; epilogue writes r*h into feat0 hidden slots and u into g_u
    gemm_tc<128, true><<<MROWS / 128, 256>>>(ru_bias, hs, nullptr);

    // conv2 Chebyshev propagations (hidden 1024 channels only)
    prop_pair<true><<<dim3(NN, 2), 128>>>(0);
    prop_pair<true><<<dim3(NN, 2), 128>>>(1);

    // c = tanh(tanh(cheb @ c_param + bias));  out = u*h + (1-u)*c  (+ tail reset)
    gemm_tc<64, false><<<MROWS / 128, 256>>>(c_bias, hs, out);
}